// round 11
// baseline (speedup 1.0000x reference)
#include <cuda_runtime.h>
#include <cuda_bf16.h>

#define Bv 4
#define Tv 512
#define Iv 512
#define Hv 8
#define Dv 512
#define Vv 32000
#define NQ4R (Vv / 4)            // 8000 float4 per row
#define HSZ 1024                 // dedup hash table slots

// scratch (allocation-free rule: __device__ globals)
__device__ int   g_leader[Bv * Iv];
__device__ float g_encW[Bv * Iv];
__device__ int   g_nu[Bv];
__device__ float g_pg[Bv * Tv];
__device__ float g_base[Bv * Tv];
__device__ float g_eb[Bv * Tv * Iv];   // e*base per (row, slot-owner i); 4MB

// ---------------------------------------------------------------------------
// Prep (measured-best shape): blocks [0,128) encW — 16 warps/block, one (b,i)
// row per warp, each lane batches 4 float4 pairs. Blocks [128,132): dedup.
// ---------------------------------------------------------------------------
__global__ __launch_bounds__(512) void prep_kernel(const int* __restrict__ tok,
                                                   const float* __restrict__ enc,
                                                   const float* __restrict__ W) {
    if (blockIdx.x < 128) {
        int row  = blockIdx.x * 16 + (threadIdx.x >> 5);   // 0..2047 = b*I+i
        int lane = threadIdx.x & 31;
        const float4* r4 = (const float4*)(enc + (long)row * Dv);
        const float4* W4 = (const float4*)W;
        float4 r0 = __ldg(&r4[lane]);
        float4 r1 = __ldg(&r4[lane + 32]);
        float4 r2 = __ldg(&r4[lane + 64]);
        float4 r3 = __ldg(&r4[lane + 96]);
        float4 w0 = __ldg(&W4[lane]);
        float4 w1 = __ldg(&W4[lane + 32]);
        float4 w2 = __ldg(&W4[lane + 64]);
        float4 w3 = __ldg(&W4[lane + 96]);
        float acc = r0.x * w0.x + r0.y * w0.y + r0.z * w0.z + r0.w * w0.w;
        acc = fmaf(r1.x, w1.x, acc); acc = fmaf(r1.y, w1.y, acc);
        acc = fmaf(r1.z, w1.z, acc); acc = fmaf(r1.w, w1.w, acc);
        acc = fmaf(r2.x, w2.x, acc); acc = fmaf(r2.y, w2.y, acc);
        acc = fmaf(r2.z, w2.z, acc); acc = fmaf(r2.w, w2.w, acc);
        acc = fmaf(r3.x, w3.x, acc); acc = fmaf(r3.y, w3.y, acc);
        acc = fmaf(r3.z, w3.z, acc); acc = fmaf(r3.w, w3.w, acc);
        #pragma unroll
        for (int o = 16; o; o >>= 1) acc += __shfl_down_sync(0xffffffffu, acc, o);
        if (lane == 0) g_encW[row] = acc;
    } else {
        __shared__ int hkey[HSZ];
        __shared__ int hval[HSZ];
        int b = blockIdx.x - 128;
        int i = threadIdx.x;
        #pragma unroll
        for (int s = i; s < HSZ; s += 512) { hkey[s] = -1; hval[s] = 0x7fffffff; }
        int me = tok[b * Iv + i];
        __syncthreads();
        unsigned h = ((unsigned)me * 2654435761u) & (HSZ - 1);
        while (true) {
            int kk = atomicCAS(&hkey[h], -1, me);
            if (kk == -1 || kk == me) break;
            h = (h + 1) & (HSZ - 1);
        }
        atomicMin(&hval[h], i);
        __syncthreads();
        int lead = hval[h];
        g_leader[b * Iv + i] = lead;
        int n = __syncthreads_count(lead == i);
        if (i == 0) g_nu[b] = n;
    }
    cudaTriggerProgrammaticLaunchCompletion();
}

// ---------------------------------------------------------------------------
// Dual block reduction: sums v1 and v2 across 512 threads with one barrier set.
// ---------------------------------------------------------------------------
__device__ __forceinline__ void block_reduce_sum2(float v1, float v2,
                                                  float* s1, float* s2,
                                                  float& r1, float& r2) {
    int lane = threadIdx.x & 31;
    int w = threadIdx.x >> 5;
    #pragma unroll
    for (int o = 16; o; o >>= 1) {
        v1 += __shfl_down_sync(0xffffffffu, v1, o);
        v2 += __shfl_down_sync(0xffffffffu, v2, o);
    }
    if (lane == 0) { s1[w] = v1; s2[w] = v2; }
    __syncthreads();
    if (w == 0) {
        float x1 = (lane < 16) ? s1[lane] : 0.f;
        float x2 = (lane < 16) ? s2[lane] : 0.f;
        #pragma unroll
        for (int o = 8; o; o >>= 1) {
            x1 += __shfl_down_sync(0xffffffffu, x1, o);
            x2 += __shfl_down_sync(0xffffffffu, x2, o);
        }
        if (lane == 0) { s1[0] = x1; s2[0] = x2; }
    }
    __syncthreads();
    r1 = s1[0];
    r2 = s2[0];
}

// ---------------------------------------------------------------------------
// Row kernel (PDL consumer of prep): prefetch attn planes (pure inputs) BEFORE
// the grid dependency sync, then use prep outputs.
// ---------------------------------------------------------------------------
__global__ __launch_bounds__(512) void row_kernel(
    const int* __restrict__ tok,
    const float* __restrict__ tar,
    const float* __restrict__ dec,
    const float* __restrict__ attn_heads,
    const float* __restrict__ W,
    const float* __restrict__ bpg,
    float* __restrict__ out)
{
    const int row = blockIdx.x;        // b*T + t
    const int b   = row >> 9;
    const int t   = row & 511;
    const int tid = threadIdx.x;

    __shared__ float ss[Iv];
    __shared__ float s1[32], s2[32];

    ss[tid] = 0.f;

    // prefetch inputs (not produced by prep) while prep finishes
    float a[Hv];
    long base_a = ((long)b * Hv) * ((long)Tv * Iv) + (long)t * Iv + tid;
    #pragma unroll
    for (int h = 0; h < Hv; h++) a[h] = __ldg(&attn_heads[base_a + (long)h * Tv * Iv]);
    float dv = __ldg(&dec[(long)row * Dv + tid]);
    float tv = __ldg(&tar[(long)row * Dv + tid]);
    float w1 = __ldg(&W[Dv + tid]);
    float w2 = __ldg(&W[2 * Dv + tid]);

    cudaGridDependencySynchronize();   // prep's g_leader/g_encW/g_nu now visible

    const int lead = g_leader[b * Iv + tid];

    float w = 0.f;
    #pragma unroll
    for (int h = 0; h < Hv; h++) w += a[h];
    w *= 0.125f;

    __syncthreads();                   // ss zeroed
    atomicAdd(&ss[lead], w);

    float acc = w * g_encW[b * Iv + tid];
    acc = fmaf(dv, w1, acc);
    acc = fmaf(tv, w2, acc);

    __syncthreads();                   // publish atomics

    const bool active = (lead == tid);
    float e = active ? expf(ss[tid]) : 0.f;

    float pgsum, esum;
    block_reduce_sum2(acc, e, s1, s2, pgsum, esum);

    const float denom = esum + (float)(Vv - g_nu[b]);
    const float base  = 1.f / denom;
    const float pg    = 1.f / (1.f + expf(-(pgsum + bpg[0])));

    g_eb[(long)row * Iv + tid] = e * base;     // 0 for inactive slots
    if (tid == 0) {
        g_pg[row]   = pg;
        g_base[row] = base;
        out[2L * Bv * Tv * Vv + row] = pg;     // p_gen (B,T)
    }
    cudaTriggerProgrammaticLaunchCompletion();
}

// ---------------------------------------------------------------------------
// Stream kernel (PDL consumer of row). One final block + one fill block per
// row (role = blockIdx parity). Plain LDG/STG (no cache hints). Role 0 runs
// the 8000-float4 row as two batch-8 passes; first pass loads pre-sync.
// ---------------------------------------------------------------------------
__global__ __launch_bounds__(512) void stream_kernel(
    const int* __restrict__ tok,
    const float* __restrict__ gen,
    float* __restrict__ out)
{
    const int role = blockIdx.x & 1;
    const int row  = blockIdx.x >> 1;      // b*T + t
    const int b    = row >> 9;
    const int tid  = threadIdx.x;

    const int v = __ldg(&tok[b * Iv + tid]);   // input: safe pre-sync

    if (role == 0) {
        // ---- final = pg*gen + (1-pg)*base ----
        const float4* g4 = (const float4*)(gen + (long)row * Vv);
        float4* f4 = (float4*)(out + (long)row * Vv);

        // pass 1 loads (slots tid .. 4095), issued before the dependency sync
        float4 r[8];
        #pragma unroll
        for (int j = 0; j < 8; j++) r[j] = g4[tid + j * 512];

        cudaGridDependencySynchronize();   // row's pg/base/eb now visible

        const float pg   = g_pg[row];
        const float base = g_base[row];
        const float omp  = 1.f - pg;
        const float pb   = omp * base;

        const int  lead = g_leader[b * Iv + tid];
        const bool act  = (lead == tid);
        float gscat = 0.f, eb = 0.f;
        if (act) {
            gscat = __ldg(&gen[(long)row * Vv + v]);
            eb    = g_eb[(long)row * Iv + tid];
        }

        // pass 1 stores
        #pragma unroll
        for (int j = 0; j < 8; j++) {
            float4 f;
            f.x = fmaf(pg, r[j].x, pb);
            f.y = fmaf(pg, r[j].y, pb);
            f.z = fmaf(pg, r[j].z, pb);
            f.w = fmaf(pg, r[j].w, pb);
            f4[tid + j * 512] = f;
        }

        // pass 2: slots 4096 .. 7999
        float4 r2[8];
        bool ok[8];
        #pragma unroll
        for (int j = 0; j < 8; j++) {
            int q = 4096 + tid + j * 512;
            ok[j] = q < NQ4R;
            if (ok[j]) r2[j] = g4[q];
        }
        #pragma unroll
        for (int j = 0; j < 8; j++) {
            if (ok[j]) {
                int q = 4096 + tid + j * 512;
                float4 f;
                f.x = fmaf(pg, r2[j].x, pb);
                f.y = fmaf(pg, r2[j].y, pb);
                f.z = fmaf(pg, r2[j].z, pb);
                f.w = fmaf(pg, r2[j].w, pb);
                f4[q] = f;
            }
        }
        __syncthreads();                  // order fixup after stream
        if (act) out[(long)row * Vv + v] = fmaf(pg, gscat, omp * eb);
    } else {
        // ---- pointer = base (+ slot fixups) ----
        cudaGridDependencySynchronize();

        const float base = g_base[row];
        const int  lead = g_leader[b * Iv + tid];
        const bool act  = (lead == tid);
        float eb = 0.f;
        if (act) eb = g_eb[(long)row * Iv + tid];

        float4* p4 = (float4*)(out + (long)(Bv * Tv) * Vv + (long)row * Vv);
        const float4 pconst = make_float4(base, base, base, base);

        #pragma unroll
        for (int j = 0; j < 16; j++) {
            int q = tid + j * 512;
            if (q < NQ4R) p4[q] = pconst;
        }
        __syncthreads();
        if (act) out[(long)(Bv * Tv) * Vv + (long)row * Vv + v] = eb;
    }
}

// ---------------------------------------------------------------------------
// Launch with PDL chaining. Inputs: inp_tokens, tar_embedded,
// generator_output, enc_output, dec_state, attn_heads, W_pgen, b_pgen.
// ---------------------------------------------------------------------------
extern "C" void kernel_launch(void* const* d_in, const int* in_sizes, int n_in,
                              void* d_out, int out_size) {
    const int*   tok  = (const int*)  d_in[0];
    const float* tar  = (const float*)d_in[1];
    const float* gen  = (const float*)d_in[2];
    const float* enc  = (const float*)d_in[3];
    const float* dec  = (const float*)d_in[4];
    const float* ah   = (const float*)d_in[5];
    const float* W    = (const float*)d_in[6];
    const float* bpg  = (const float*)d_in[7];
    float* out = (float*)d_out;

    prep_kernel<<<132, 512>>>(tok, enc, W);

    cudaLaunchAttribute attr[1];
    attr[0].id = cudaLaunchAttributeProgrammaticStreamSerialization;
    attr[0].val.programmaticStreamSerializationAllowed = 1;

    {
        cudaLaunchConfig_t cfg = {};
        cfg.gridDim  = dim3(Bv * Tv);
        cfg.blockDim = dim3(512);
        cfg.attrs    = attr;
        cfg.numAttrs = 1;
        cudaLaunchKernelEx(&cfg, row_kernel, tok, tar, dec, ah, W, bpg, out);
    }
    {
        cudaLaunchConfig_t cfg = {};
        cfg.gridDim  = dim3(2 * Bv * Tv);
        cfg.blockDim = dim3(512);
        cfg.attrs    = attr;
        cfg.numAttrs = 1;
        cudaLaunchKernelEx(&cfg, stream_kernel, tok, gen, out);
    }
}

// round 12
// speedup vs baseline: 1.0161x; 1.0161x over previous
#include <cuda_runtime.h>
#include <cuda_bf16.h>

#define Bv 4
#define Tv 512
#define Iv 512
#define Hv 8
#define Dv 512
#define Vv 32000
#define HCHUNK (Vv / 2)          // 16000 floats per final half-row
#define HQ4    (HCHUNK / 4)      // 4000 float4 per half
#define NQ4R   (Vv / 4)          // 8000 float4 per row
#define HSZ 1024                 // dedup hash table slots

// scratch (allocation-free rule: __device__ globals)
__device__ int   g_leader[Bv * Iv];
__device__ float g_encW[Bv * Iv];
__device__ int   g_nu[Bv];
__device__ float g_pg[Bv * Tv];
__device__ float g_base[Bv * Tv];
__device__ float g_eb[Bv * Tv * Iv];   // e*base per (row, slot-owner i); 4MB

// ---------------------------------------------------------------------------
// Prep (measured-best shape): blocks [0,128) encW — 16 warps/block, one (b,i)
// row per warp, each lane batches 4 float4 pairs. Blocks [128,132): dedup.
// ---------------------------------------------------------------------------
__global__ __launch_bounds__(512) void prep_kernel(const int* __restrict__ tok,
                                                   const float* __restrict__ enc,
                                                   const float* __restrict__ W) {
    if (blockIdx.x < 128) {
        int row  = blockIdx.x * 16 + (threadIdx.x >> 5);   // 0..2047 = b*I+i
        int lane = threadIdx.x & 31;
        const float4* r4 = (const float4*)(enc + (long)row * Dv);
        const float4* W4 = (const float4*)W;
        float4 r0 = __ldg(&r4[lane]);
        float4 r1 = __ldg(&r4[lane + 32]);
        float4 r2 = __ldg(&r4[lane + 64]);
        float4 r3 = __ldg(&r4[lane + 96]);
        float4 w0 = __ldg(&W4[lane]);
        float4 w1 = __ldg(&W4[lane + 32]);
        float4 w2 = __ldg(&W4[lane + 64]);
        float4 w3 = __ldg(&W4[lane + 96]);
        float acc = r0.x * w0.x + r0.y * w0.y + r0.z * w0.z + r0.w * w0.w;
        acc = fmaf(r1.x, w1.x, acc); acc = fmaf(r1.y, w1.y, acc);
        acc = fmaf(r1.z, w1.z, acc); acc = fmaf(r1.w, w1.w, acc);
        acc = fmaf(r2.x, w2.x, acc); acc = fmaf(r2.y, w2.y, acc);
        acc = fmaf(r2.z, w2.z, acc); acc = fmaf(r2.w, w2.w, acc);
        acc = fmaf(r3.x, w3.x, acc); acc = fmaf(r3.y, w3.y, acc);
        acc = fmaf(r3.z, w3.z, acc); acc = fmaf(r3.w, w3.w, acc);
        #pragma unroll
        for (int o = 16; o; o >>= 1) acc += __shfl_down_sync(0xffffffffu, acc, o);
        if (lane == 0) g_encW[row] = acc;
    } else {
        __shared__ int hkey[HSZ];
        __shared__ int hval[HSZ];
        int b = blockIdx.x - 128;
        int i = threadIdx.x;
        #pragma unroll
        for (int s = i; s < HSZ; s += 512) { hkey[s] = -1; hval[s] = 0x7fffffff; }
        int me = tok[b * Iv + i];
        __syncthreads();
        unsigned h = ((unsigned)me * 2654435761u) & (HSZ - 1);
        while (true) {
            int kk = atomicCAS(&hkey[h], -1, me);
            if (kk == -1 || kk == me) break;
            h = (h + 1) & (HSZ - 1);
        }
        atomicMin(&hval[h], i);
        __syncthreads();
        int lead = hval[h];
        g_leader[b * Iv + i] = lead;
        int n = __syncthreads_count(lead == i);
        if (i == 0) g_nu[b] = n;
    }
    cudaTriggerProgrammaticLaunchCompletion();
}

// ---------------------------------------------------------------------------
// Dual block reduction: sums v1 and v2 across 512 threads with one barrier set.
// ---------------------------------------------------------------------------
__device__ __forceinline__ void block_reduce_sum2(float v1, float v2,
                                                  float* s1, float* s2,
                                                  float& r1, float& r2) {
    int lane = threadIdx.x & 31;
    int w = threadIdx.x >> 5;
    #pragma unroll
    for (int o = 16; o; o >>= 1) {
        v1 += __shfl_down_sync(0xffffffffu, v1, o);
        v2 += __shfl_down_sync(0xffffffffu, v2, o);
    }
    if (lane == 0) { s1[w] = v1; s2[w] = v2; }
    __syncthreads();
    if (w == 0) {
        float x1 = (lane < 16) ? s1[lane] : 0.f;
        float x2 = (lane < 16) ? s2[lane] : 0.f;
        #pragma unroll
        for (int o = 8; o; o >>= 1) {
            x1 += __shfl_down_sync(0xffffffffu, x1, o);
            x2 += __shfl_down_sync(0xffffffffu, x2, o);
        }
        if (lane == 0) { s1[0] = x1; s2[0] = x2; }
    }
    __syncthreads();
    r1 = s1[0];
    r2 = s2[0];
}

// ---------------------------------------------------------------------------
// Row kernel (PDL consumer of prep): prefetch attn planes (pure inputs) BEFORE
// the grid dependency sync, then use prep outputs.
// ---------------------------------------------------------------------------
__global__ __launch_bounds__(512) void row_kernel(
    const int* __restrict__ tok,
    const float* __restrict__ tar,
    const float* __restrict__ dec,
    const float* __restrict__ attn_heads,
    const float* __restrict__ W,
    const float* __restrict__ bpg,
    float* __restrict__ out)
{
    const int row = blockIdx.x;        // b*T + t
    const int b   = row >> 9;
    const int t   = row & 511;
    const int tid = threadIdx.x;

    __shared__ float ss[Iv];
    __shared__ float s1[32], s2[32];

    ss[tid] = 0.f;

    // prefetch inputs (not produced by prep) while prep finishes
    float a[Hv];
    long base_a = ((long)b * Hv) * ((long)Tv * Iv) + (long)t * Iv + tid;
    #pragma unroll
    for (int h = 0; h < Hv; h++) a[h] = __ldg(&attn_heads[base_a + (long)h * Tv * Iv]);
    float dv = __ldg(&dec[(long)row * Dv + tid]);
    float tv = __ldg(&tar[(long)row * Dv + tid]);
    float w1 = __ldg(&W[Dv + tid]);
    float w2 = __ldg(&W[2 * Dv + tid]);

    cudaGridDependencySynchronize();   // prep's g_leader/g_encW/g_nu now visible

    const int lead = g_leader[b * Iv + tid];

    float w = 0.f;
    #pragma unroll
    for (int h = 0; h < Hv; h++) w += a[h];
    w *= 0.125f;

    __syncthreads();                   // ss zeroed
    atomicAdd(&ss[lead], w);

    float acc = w * g_encW[b * Iv + tid];
    acc = fmaf(dv, w1, acc);
    acc = fmaf(tv, w2, acc);

    __syncthreads();                   // publish atomics

    const bool active = (lead == tid);
    float e = active ? expf(ss[tid]) : 0.f;

    float pgsum, esum;
    block_reduce_sum2(acc, e, s1, s2, pgsum, esum);

    const float denom = esum + (float)(Vv - g_nu[b]);
    const float base  = 1.f / denom;
    const float pg    = 1.f / (1.f + expf(-(pgsum + bpg[0])));

    g_eb[(long)row * Iv + tid] = e * base;     // 0 for inactive slots
    if (tid == 0) {
        g_pg[row]   = pg;
        g_base[row] = base;
        out[2L * Bv * Tv * Vv + row] = pg;     // p_gen (B,T)
    }
    cudaTriggerProgrammaticLaunchCompletion();
}

// ---------------------------------------------------------------------------
// Stream kernel (PDL consumer of row). THREE equal-traffic blocks per row:
//  role 0/1: final half-row — 64KB read + 64KB write, all loads pre-sync.
//  role 2:   fill full row  — 128KB write.
// Plain LDG/STG (hints hurt stores, neutral on loads — measured).
// ---------------------------------------------------------------------------
__global__ __launch_bounds__(512) void stream_kernel(
    const int* __restrict__ tok,
    const float* __restrict__ gen,
    float* __restrict__ out)
{
    const int idx  = blockIdx.x;
    const int row  = idx / 3;              // b*T + t
    const int role = idx - row * 3;
    const int b    = row >> 9;
    const int tid  = threadIdx.x;

    const int v = __ldg(&tok[b * Iv + tid]);   // input: safe pre-sync

    if (role < 2) {
        // ---- final half-row = pg*gen + (1-pg)*base ----
        const int lo  = role * HCHUNK;
        const int q0  = (lo >> 2) + tid;
        const float4* g4 = (const float4*)(gen + (long)row * Vv);
        float4* f4 = (float4*)(out + (long)row * Vv);

        // entire half-row read issued BEFORE the dependency sync
        float4 r[8];
        bool ok[8];
        #pragma unroll
        for (int j = 0; j < 8; j++) {
            ok[j] = (tid + j * 512) < HQ4;
            if (ok[j]) r[j] = g4[q0 + j * 512];
        }

        cudaGridDependencySynchronize();   // row's pg/base/eb now visible

        const float pg   = g_pg[row];
        const float base = g_base[row];
        const float omp  = 1.f - pg;
        const float pb   = omp * base;

        const int  lead = g_leader[b * Iv + tid];
        const bool act  = (lead == tid) && (v >= lo) && (v < lo + HCHUNK);
        float gscat = 0.f, eb = 0.f;
        if (act) {
            gscat = __ldg(&gen[(long)row * Vv + v]);
            eb    = g_eb[(long)row * Iv + tid];
        }

        #pragma unroll
        for (int j = 0; j < 8; j++) {
            if (ok[j]) {
                float4 f;
                f.x = fmaf(pg, r[j].x, pb);
                f.y = fmaf(pg, r[j].y, pb);
                f.z = fmaf(pg, r[j].z, pb);
                f.w = fmaf(pg, r[j].w, pb);
                f4[q0 + j * 512] = f;
            }
        }
        __syncthreads();                  // order fixup after stream
        if (act) out[(long)row * Vv + v] = fmaf(pg, gscat, omp * eb);
    } else {
        // ---- pointer = base (+ slot fixups), full row ----
        cudaGridDependencySynchronize();

        const float base = g_base[row];
        const int  lead = g_leader[b * Iv + tid];
        const bool act  = (lead == tid);
        float eb = 0.f;
        if (act) eb = g_eb[(long)row * Iv + tid];

        float4* p4 = (float4*)(out + (long)(Bv * Tv) * Vv + (long)row * Vv);
        const float4 pconst = make_float4(base, base, base, base);

        #pragma unroll
        for (int j = 0; j < 16; j++) {
            int q = tid + j * 512;
            if (q < NQ4R) p4[q] = pconst;
        }
        __syncthreads();
        if (act) out[(long)(Bv * Tv) * Vv + (long)row * Vv + v] = eb;
    }
}

// ---------------------------------------------------------------------------
// Launch with PDL chaining. Inputs: inp_tokens, tar_embedded,
// generator_output, enc_output, dec_state, attn_heads, W_pgen, b_pgen.
// ---------------------------------------------------------------------------
extern "C" void kernel_launch(void* const* d_in, const int* in_sizes, int n_in,
                              void* d_out, int out_size) {
    const int*   tok  = (const int*)  d_in[0];
    const float* tar  = (const float*)d_in[1];
    const float* gen  = (const float*)d_in[2];
    const float* enc  = (const float*)d_in[3];
    const float* dec  = (const float*)d_in[4];
    const float* ah   = (const float*)d_in[5];
    const float* W    = (const float*)d_in[6];
    const float* bpg  = (const float*)d_in[7];
    float* out = (float*)d_out;

    prep_kernel<<<132, 512>>>(tok, enc, W);

    cudaLaunchAttribute attr[1];
    attr[0].id = cudaLaunchAttributeProgrammaticStreamSerialization;
    attr[0].val.programmaticStreamSerializationAllowed = 1;

    {
        cudaLaunchConfig_t cfg = {};
        cfg.gridDim  = dim3(Bv * Tv);
        cfg.blockDim = dim3(512);
        cfg.attrs    = attr;
        cfg.numAttrs = 1;
        cudaLaunchKernelEx(&cfg, row_kernel, tok, tar, dec, ah, W, bpg, out);
    }
    {
        cudaLaunchConfig_t cfg = {};
        cfg.gridDim  = dim3(3 * Bv * Tv);
        cfg.blockDim = dim3(512);
        cfg.attrs    = attr;
        cfg.numAttrs = 1;
        cudaLaunchKernelEx(&cfg, stream_kernel, tok, gen, out);
    }
}

// round 13
// speedup vs baseline: 1.0317x; 1.0154x over previous
#include <cuda_runtime.h>
#include <cuda_bf16.h>

#define Bv 4
#define Tv 512
#define Iv 512
#define Hv 8
#define Dv 512
#define Vv 32000
#define HCHUNK (Vv / 2)          // 16000 floats per final half-row
#define HQ4    (HCHUNK / 4)      // 4000 float4 per half
#define NQ4R   (Vv / 4)          // 8000 float4 per row
#define HSZ 1024                 // dedup hash table slots

// scratch (allocation-free rule: __device__ globals)
__device__ int   g_leader[Bv * Iv];
__device__ float g_encW[Bv * Iv];
__device__ int   g_nu[Bv];
__device__ float g_pg[Bv * Tv];
__device__ float g_base[Bv * Tv];
__device__ float g_eb[Bv * Tv * Iv];   // e*base per (row, slot-owner i); 4MB

// ---------------------------------------------------------------------------
// Prep: trigger FIRST (dependent may launch + prefetch concurrently; its
// GridDependencySynchronize still waits for our completion). Blocks [0,128)
// encW — 16 warps/block, one (b,i) row per warp, 4 float4 pairs per lane.
// Blocks [128,132): per-batch dedup via smem hash.
// ---------------------------------------------------------------------------
__global__ __launch_bounds__(512) void prep_kernel(const int* __restrict__ tok,
                                                   const float* __restrict__ enc,
                                                   const float* __restrict__ W) {
    cudaTriggerProgrammaticLaunchCompletion();
    if (blockIdx.x < 128) {
        int row  = blockIdx.x * 16 + (threadIdx.x >> 5);   // 0..2047 = b*I+i
        int lane = threadIdx.x & 31;
        const float4* r4 = (const float4*)(enc + (long)row * Dv);
        const float4* W4 = (const float4*)W;
        float4 r0 = __ldg(&r4[lane]);
        float4 r1 = __ldg(&r4[lane + 32]);
        float4 r2 = __ldg(&r4[lane + 64]);
        float4 r3 = __ldg(&r4[lane + 96]);
        float4 w0 = __ldg(&W4[lane]);
        float4 w1 = __ldg(&W4[lane + 32]);
        float4 w2 = __ldg(&W4[lane + 64]);
        float4 w3 = __ldg(&W4[lane + 96]);
        float acc = r0.x * w0.x + r0.y * w0.y + r0.z * w0.z + r0.w * w0.w;
        acc = fmaf(r1.x, w1.x, acc); acc = fmaf(r1.y, w1.y, acc);
        acc = fmaf(r1.z, w1.z, acc); acc = fmaf(r1.w, w1.w, acc);
        acc = fmaf(r2.x, w2.x, acc); acc = fmaf(r2.y, w2.y, acc);
        acc = fmaf(r2.z, w2.z, acc); acc = fmaf(r2.w, w2.w, acc);
        acc = fmaf(r3.x, w3.x, acc); acc = fmaf(r3.y, w3.y, acc);
        acc = fmaf(r3.z, w3.z, acc); acc = fmaf(r3.w, w3.w, acc);
        #pragma unroll
        for (int o = 16; o; o >>= 1) acc += __shfl_down_sync(0xffffffffu, acc, o);
        if (lane == 0) g_encW[row] = acc;
    } else {
        __shared__ int hkey[HSZ];
        __shared__ int hval[HSZ];
        int b = blockIdx.x - 128;
        int i = threadIdx.x;
        #pragma unroll
        for (int s = i; s < HSZ; s += 512) { hkey[s] = -1; hval[s] = 0x7fffffff; }
        int me = tok[b * Iv + i];
        __syncthreads();
        unsigned h = ((unsigned)me * 2654435761u) & (HSZ - 1);
        while (true) {
            int kk = atomicCAS(&hkey[h], -1, me);
            if (kk == -1 || kk == me) break;
            h = (h + 1) & (HSZ - 1);
        }
        atomicMin(&hval[h], i);
        __syncthreads();
        int lead = hval[h];
        g_leader[b * Iv + i] = lead;
        int n = __syncthreads_count(lead == i);
        if (i == 0) g_nu[b] = n;
    }
}

// ---------------------------------------------------------------------------
// Dual block reduction: sums v1 and v2 across 512 threads with one barrier set.
// ---------------------------------------------------------------------------
__device__ __forceinline__ void block_reduce_sum2(float v1, float v2,
                                                  float* s1, float* s2,
                                                  float& r1, float& r2) {
    int lane = threadIdx.x & 31;
    int w = threadIdx.x >> 5;
    #pragma unroll
    for (int o = 16; o; o >>= 1) {
        v1 += __shfl_down_sync(0xffffffffu, v1, o);
        v2 += __shfl_down_sync(0xffffffffu, v2, o);
    }
    if (lane == 0) { s1[w] = v1; s2[w] = v2; }
    __syncthreads();
    if (w == 0) {
        float x1 = (lane < 16) ? s1[lane] : 0.f;
        float x2 = (lane < 16) ? s2[lane] : 0.f;
        #pragma unroll
        for (int o = 8; o; o >>= 1) {
            x1 += __shfl_down_sync(0xffffffffu, x1, o);
            x2 += __shfl_down_sync(0xffffffffu, x2, o);
        }
        if (lane == 0) { s1[0] = x1; s2[0] = x2; }
    }
    __syncthreads();
    r1 = s1[0];
    r2 = s2[0];
}

// ---------------------------------------------------------------------------
// Row kernel (PDL consumer of prep): trigger FIRST so the stream kernel can
// launch and prefetch gen concurrently with our whole execution. Prefetch our
// own inputs before the dependency sync on prep.
// ---------------------------------------------------------------------------
__global__ __launch_bounds__(512) void row_kernel(
    const int* __restrict__ tok,
    const float* __restrict__ tar,
    const float* __restrict__ dec,
    const float* __restrict__ attn_heads,
    const float* __restrict__ W,
    const float* __restrict__ bpg,
    float* __restrict__ out)
{
    cudaTriggerProgrammaticLaunchCompletion();
    const int row = blockIdx.x;        // b*T + t
    const int b   = row >> 9;
    const int t   = row & 511;
    const int tid = threadIdx.x;

    __shared__ float ss[Iv];
    __shared__ float s1[32], s2[32];

    ss[tid] = 0.f;

    // prefetch inputs (not produced by prep) while prep finishes
    float a[Hv];
    long base_a = ((long)b * Hv) * ((long)Tv * Iv) + (long)t * Iv + tid;
    #pragma unroll
    for (int h = 0; h < Hv; h++) a[h] = __ldg(&attn_heads[base_a + (long)h * Tv * Iv]);
    float dv = __ldg(&dec[(long)row * Dv + tid]);
    float tv = __ldg(&tar[(long)row * Dv + tid]);
    float w1 = __ldg(&W[Dv + tid]);
    float w2 = __ldg(&W[2 * Dv + tid]);

    cudaGridDependencySynchronize();   // prep's g_leader/g_encW/g_nu now visible

    const int lead = g_leader[b * Iv + tid];

    float w = 0.f;
    #pragma unroll
    for (int h = 0; h < Hv; h++) w += a[h];
    w *= 0.125f;

    __syncthreads();                   // ss zeroed
    atomicAdd(&ss[lead], w);

    float acc = w * g_encW[b * Iv + tid];
    acc = fmaf(dv, w1, acc);
    acc = fmaf(tv, w2, acc);

    __syncthreads();                   // publish atomics

    const bool active = (lead == tid);
    float e = active ? expf(ss[tid]) : 0.f;

    float pgsum, esum;
    block_reduce_sum2(acc, e, s1, s2, pgsum, esum);

    const float denom = esum + (float)(Vv - g_nu[b]);
    const float base  = 1.f / denom;
    const float pg    = 1.f / (1.f + expf(-(pgsum + bpg[0])));

    g_eb[(long)row * Iv + tid] = e * base;     // 0 for inactive slots
    if (tid == 0) {
        g_pg[row]   = pg;
        g_base[row] = base;
        out[2L * Bv * Tv * Vv + row] = pg;     // p_gen (B,T)
    }
}

// ---------------------------------------------------------------------------
// Stream kernel (PDL consumer of row). THREE equal-traffic blocks per row:
//  role 0/1: final half-row — 64KB read + 64KB write, all loads pre-sync.
//  role 2:   fill full row  — 128KB write.
// Plain LDG/STG (hints hurt stores, neutral on loads — measured).
// ---------------------------------------------------------------------------
__global__ __launch_bounds__(512) void stream_kernel(
    const int* __restrict__ tok,
    const float* __restrict__ gen,
    float* __restrict__ out)
{
    const int idx  = blockIdx.x;
    const int row  = idx / 3;              // b*T + t
    const int role = idx - row * 3;
    const int b    = row >> 9;
    const int tid  = threadIdx.x;

    const int v = __ldg(&tok[b * Iv + tid]);   // input: safe pre-sync

    if (role < 2) {
        // ---- final half-row = pg*gen + (1-pg)*base ----
        const int lo  = role * HCHUNK;
        const int q0  = (lo >> 2) + tid;
        const float4* g4 = (const float4*)(gen + (long)row * Vv);
        float4* f4 = (float4*)(out + (long)row * Vv);

        // entire half-row read issued BEFORE the dependency sync
        float4 r[8];
        bool ok[8];
        #pragma unroll
        for (int j = 0; j < 8; j++) {
            ok[j] = (tid + j * 512) < HQ4;
            if (ok[j]) r[j] = g4[q0 + j * 512];
        }

        cudaGridDependencySynchronize();   // row's pg/base/eb now visible

        const float pg   = g_pg[row];
        const float base = g_base[row];
        const float omp  = 1.f - pg;
        const float pb   = omp * base;

        const int  lead = g_leader[b * Iv + tid];
        const bool act  = (lead == tid) && (v >= lo) && (v < lo + HCHUNK);
        float gscat = 0.f, eb = 0.f;
        if (act) {
            gscat = __ldg(&gen[(long)row * Vv + v]);
            eb    = g_eb[(long)row * Iv + tid];
        }

        #pragma unroll
        for (int j = 0; j < 8; j++) {
            if (ok[j]) {
                float4 f;
                f.x = fmaf(pg, r[j].x, pb);
                f.y = fmaf(pg, r[j].y, pb);
                f.z = fmaf(pg, r[j].z, pb);
                f.w = fmaf(pg, r[j].w, pb);
                f4[q0 + j * 512] = f;
            }
        }
        __syncthreads();                  // order fixup after stream
        if (act) out[(long)row * Vv + v] = fmaf(pg, gscat, omp * eb);
    } else {
        // ---- pointer = base (+ slot fixups), full row ----
        cudaGridDependencySynchronize();

        const float base = g_base[row];
        const int  lead = g_leader[b * Iv + tid];
        const bool act  = (lead == tid);
        float eb = 0.f;
        if (act) eb = g_eb[(long)row * Iv + tid];

        float4* p4 = (float4*)(out + (long)(Bv * Tv) * Vv + (long)row * Vv);
        const float4 pconst = make_float4(base, base, base, base);

        #pragma unroll
        for (int j = 0; j < 16; j++) {
            int q = tid + j * 512;
            if (q < NQ4R) p4[q] = pconst;
        }
        __syncthreads();
        if (act) out[(long)(Bv * Tv) * Vv + (long)row * Vv + v] = eb;
    }
}

// ---------------------------------------------------------------------------
// Launch with PDL chaining. Inputs: inp_tokens, tar_embedded,
// generator_output, enc_output, dec_state, attn_heads, W_pgen, b_pgen.
// ---------------------------------------------------------------------------
extern "C" void kernel_launch(void* const* d_in, const int* in_sizes, int n_in,
                              void* d_out, int out_size) {
    const int*   tok  = (const int*)  d_in[0];
    const float* tar  = (const float*)d_in[1];
    const float* gen  = (const float*)d_in[2];
    const float* enc  = (const float*)d_in[3];
    const float* dec  = (const float*)d_in[4];
    const float* ah   = (const float*)d_in[5];
    const float* W    = (const float*)d_in[6];
    const float* bpg  = (const float*)d_in[7];
    float* out = (float*)d_out;

    prep_kernel<<<132, 512>>>(tok, enc, W);

    cudaLaunchAttribute attr[1];
    attr[0].id = cudaLaunchAttributeProgrammaticStreamSerialization;
    attr[0].val.programmaticStreamSerializationAllowed = 1;

    {
        cudaLaunchConfig_t cfg = {};
        cfg.gridDim  = dim3(Bv * Tv);
        cfg.blockDim = dim3(512);
        cfg.attrs    = attr;
        cfg.numAttrs = 1;
        cudaLaunchKernelEx(&cfg, row_kernel, tok, tar, dec, ah, W, bpg, out);
    }
    {
        cudaLaunchConfig_t cfg = {};
        cfg.gridDim  = dim3(3 * Bv * Tv);
        cfg.blockDim = dim3(512);
        cfg.attrs    = attr;
        cfg.numAttrs = 1;
        cudaLaunchKernelEx(&cfg, stream_kernel, tok, gen, out);
    }
}